// round 5
// baseline (speedup 1.0000x reference)
#include <cuda_runtime.h>

static constexpr int D_CH  = 4096;   // channels
static constexpr int L_SEQ = 4096;   // sequence length
static constexpr int TPB   = 256;    // one row per block, 16 elems/thread
static constexpr int V4_PER_ROW = L_SEQ / 4;  // 1024 int4 per row (int32 elems)

__global__ void __launch_bounds__(TPB, 1)
qconv_silu_kernel(const int4* __restrict__ x,      // int8 values promoted to int32
                  const int4* __restrict__ w,      // [D,4] int32 -> one int4 per channel
                  const int*  __restrict__ bias,   // [D] int32
                  const float* __restrict__ p_sin,
                  const float* __restrict__ p_sw,
                  const float* __restrict__ p_sout,
                  const float* __restrict__ p_sb,
                  float4* __restrict__ out)        // output promoted to float32
{
    const int  row  = blockIdx.x;            // b*D + d
    const int  d    = row & (D_CH - 1);
    const int  t    = threadIdx.x;
    const long base = (long)row * V4_PER_ROW + 4 * t;   // first int4 of this thread

    // causal tail: x[16t-4 .. 16t-1]; zeros at row start = left pad (W-1)
    int4 prev = (t == 0) ? make_int4(0, 0, 0, 0) : x[base - 1];

    const int4 wv = w[d];                    // w0..w3 for this channel
    const float sxw     = __ldg(p_sin) * __ldg(p_sw);
    const float bf      = (float)bias[d] * __ldg(p_sb);
    const float inv_out = 1.0f / __ldg(p_sout);

    // rolling window: x[l-3], x[l-2], x[l-1]
    int xm3 = prev.y, xm2 = prev.z, xm1 = prev.w;

#pragma unroll
    for (int g = 0; g < 4; ++g) {
        const int4 cur = x[base + g];
        const int cc[4] = {cur.x, cur.y, cur.z, cur.w};
        float4 o;
        float* op = (float*)&o;
#pragma unroll
        for (int j = 0; j < 4; ++j) {
            const int xc = cc[j];
            // cross-correlation (lax.conv): y[l] = x[l-3]w0 + x[l-2]w1 + x[l-1]w2 + x[l]w3
            // exact in int32: |acc| <= 4*128*128 = 65536
            const int acc = xm3 * wv.x + xm2 * wv.y + xm1 * wv.z + xc * wv.w;
            float y = (float)acc * sxw + bf;
            // SiLU: y * sigmoid(y); |y| <= ~8.2 so __expf is accurate enough
            y = y / (1.0f + __expf(-y));
            // requant: round-half-even matches jnp.round, then clip to int8 range
            float r = rintf(y * inv_out);
            op[j] = fminf(fmaxf(r, -128.0f), 127.0f);
            xm3 = xm2; xm2 = xm1; xm1 = xc;
        }
        out[base + g] = o;
    }
}

extern "C" void kernel_launch(void* const* d_in, const int* in_sizes, int n_in,
                              void* d_out, int out_size)
{
    const int4* x    = (const int4*)d_in[0];
    const int4* w    = (const int4*)d_in[1];
    const int*  bias = (const int*)d_in[2];
    const float* sin_ = (const float*)d_in[3];
    const float* sw_  = (const float*)d_in[4];
    const float* sout = (const float*)d_in[5];
    const float* sb_  = (const float*)d_in[6];

    const int rows = in_sizes[0] / L_SEQ;   // B*D = 8192
    qconv_silu_kernel<<<rows, TPB>>>(x, w, bias, sin_, sw_, sout, sb_,
                                     (float4*)d_out);
}

// round 6
// speedup vs baseline: 1.1166x; 1.1166x over previous
#include <cuda_runtime.h>

static constexpr int D_CH  = 4096;   // channels
static constexpr int L_SEQ = 4096;   // sequence length
static constexpr int TPB   = 256;    // one row per block, 16 elems/thread
static constexpr int V4_PER_ROW = L_SEQ / 4;  // 1024 int4 per row (int32 elems)

__global__ void __launch_bounds__(TPB)
qconv_silu_kernel(const int4* __restrict__ x,      // int8 values promoted to int32
                  const int4* __restrict__ w,      // [D,4] int32 -> one int4 per channel
                  const int*  __restrict__ bias,   // [D] int32
                  const float* __restrict__ p_sin,
                  const float* __restrict__ p_sw,
                  const float* __restrict__ p_sout,
                  const float* __restrict__ p_sb,
                  float4* __restrict__ out)        // output promoted to float32
{
    const int  row  = blockIdx.x;            // b*D + d
    const int  d    = row & (D_CH - 1);
    const int  t    = threadIdx.x;
    const long base = (long)row * V4_PER_ROW + 4 * t;   // first int4 of this thread

    // Front-batch all loads for max MLP. Tail (x[16t-4..16t-1]) is an L1 hit:
    // it lives in the neighboring thread's payload line.
    const int4 c0 = x[base + 0];
    const int4 c1 = x[base + 1];
    const int4 c2 = x[base + 2];
    const int4 c3 = x[base + 3];
    const int4 prev = (t == 0) ? make_int4(0, 0, 0, 0) : __ldg(&x[base - 1]);

    const int4 wv = w[d];                    // w0..w3 for this channel
    const float sxw     = __ldg(p_sin) * __ldg(p_sw);
    const float bf      = (float)bias[d] * __ldg(p_sb);
    const float inv_out = 1.0f / __ldg(p_sout);

    // rolling causal window: x[l-3], x[l-2], x[l-1]
    int xm3 = prev.y, xm2 = prev.z, xm1 = prev.w;

    const int4 cc[4] = {c0, c1, c2, c3};

#pragma unroll
    for (int g = 0; g < 4; ++g) {
        const int e[4] = {cc[g].x, cc[g].y, cc[g].z, cc[g].w};
        float4 o;
        float* op = (float*)&o;
#pragma unroll
        for (int j = 0; j < 4; ++j) {
            const int xc = e[j];
            // cross-correlation (lax.conv): y[l] = x[l-3]w0 + x[l-2]w1 + x[l-1]w2 + x[l]w3
            // exact in int32: |acc| <= 4*128*128 = 65536
            const int acc = xm3 * wv.x + xm2 * wv.y + xm1 * wv.z + xc * wv.w;
            const float y = (float)acc * sxw + bf;
            // SiLU via fast-approx division: RCP.approx + MUL (2 ulp; quant slack is huge)
            const float s = y * __fdividef(1.0f, 1.0f + __expf(-y));
            // requant: round-half-even matches jnp.round, then clip to int8 range
            const float r = rintf(s * inv_out);
            op[j] = fminf(fmaxf(r, -128.0f), 127.0f);
            xm3 = xm2; xm2 = xm1; xm1 = xc;
        }
        // streaming store: output is never re-read -> evict-first
        __stcs(&out[base + g], o);
    }
}

extern "C" void kernel_launch(void* const* d_in, const int* in_sizes, int n_in,
                              void* d_out, int out_size)
{
    const int4* x    = (const int4*)d_in[0];
    const int4* w    = (const int4*)d_in[1];
    const int*  bias = (const int*)d_in[2];
    const float* sin_ = (const float*)d_in[3];
    const float* sw_  = (const float*)d_in[4];
    const float* sout = (const float*)d_in[5];
    const float* sb_  = (const float*)d_in[6];

    const int rows = in_sizes[0] / L_SEQ;   // B*D = 8192
    qconv_silu_kernel<<<rows, TPB>>>(x, w, bias, sin_, sw_, sout, sb_,
                                     (float4*)d_out);
}

// round 7
// speedup vs baseline: 1.2406x; 1.1110x over previous
#include <cuda_runtime.h>

static constexpr int D_CH  = 4096;   // channels
static constexpr int L_SEQ = 4096;   // sequence length
static constexpr int TPB   = 256;    // 8 warps; each warp owns a contiguous 512-elem segment
static constexpr int V4_PER_ROW = L_SEQ / 4;  // 1024 int4 per row

__global__ void __launch_bounds__(TPB)
qconv_silu_kernel(const int4* __restrict__ x,      // int8 promoted to int32
                  const int4* __restrict__ w,      // [D,4] int32
                  const int*  __restrict__ bias,   // [D] int32
                  const float* __restrict__ p_sin,
                  const float* __restrict__ p_sw,
                  const float* __restrict__ p_sout,
                  const float* __restrict__ p_sb,
                  float4* __restrict__ out)        // float32 out
{
    const int  row  = blockIdx.x;            // b*D + d
    const int  d    = row & (D_CH - 1);
    const int  lane = threadIdx.x & 31;
    const int  wp   = threadIdx.x >> 5;      // warp id in block
    const long rowb = (long)row * V4_PER_ROW;
    const int  segb = 128 * wp;              // warp's first int4 within the row

    // Coalesced loads: lanes 0..31 read consecutive int4 -> 4 lines per LDG.128
    int4 c[4];
#pragma unroll
    for (int k = 0; k < 4; ++k)
        c[k] = x[rowb + segb + 32 * k + lane];

    // Carry chunk = int4 preceding this warp's segment (zeros at row start = causal pad).
    // Only lane 31 needs it (it is the shuffle sender for lane 0).
    int4 carry = make_int4(0, 0, 0, 0);
    if (lane == 31 && wp != 0)
        carry = __ldg(&x[rowb + segb - 1]);

    const int4 wv = w[d];
    const float sxw     = __ldg(p_sin) * __ldg(p_sw);
    const float bf      = (float)bias[d] * __ldg(p_sb);
    const float inv_out = 1.0f / __ldg(p_sout);

    const int src = (lane + 31) & 31;        // rotate-up-by-1: lane 0 receives from lane 31

#pragma unroll
    for (int k = 0; k < 4; ++k) {
        // Previous chunk for this lane's current chunk:
        //   lanes 1..31 <- neighbor lane's c[k];  lane 0 <- lane31's previous-iter chunk.
        const int4 pk = (k == 0) ? carry : c[k - 1];
        const int vy = (lane == 31) ? pk.y : c[k].y;
        const int vz = (lane == 31) ? pk.z : c[k].z;
        const int vw = (lane == 31) ? pk.w : c[k].w;
        int xm3 = __shfl_sync(0xffffffffu, vy, src);
        int xm2 = __shfl_sync(0xffffffffu, vz, src);
        int xm1 = __shfl_sync(0xffffffffu, vw, src);

        const int e[4] = {c[k].x, c[k].y, c[k].z, c[k].w};
        float4 o;
        float* op = (float*)&o;
#pragma unroll
        for (int j = 0; j < 4; ++j) {
            const int xc = e[j];
            // cross-correlation: y[l] = x[l-3]w0 + x[l-2]w1 + x[l-1]w2 + x[l]w3 (exact int32)
            const int acc = xm3 * wv.x + xm2 * wv.y + xm1 * wv.z + xc * wv.w;
            const float y = (float)acc * sxw + bf;
            // SiLU with fast-approx reciprocal (2 ulp; quantization slack is huge)
            const float s = y * __fdividef(1.0f, 1.0f + __expf(-y));
            // requant: round-half-even (rintf) matches jnp.round, clip to int8 range
            const float r = rintf(s * inv_out);
            op[j] = fminf(fmaxf(r, -128.0f), 127.0f);
            xm3 = xm2; xm2 = xm1; xm1 = xc;
        }
        // Coalesced streaming store: 4 lines per STG.128, evict-first
        __stcs(&out[rowb + segb + 32 * k + lane], o);
    }
}

extern "C" void kernel_launch(void* const* d_in, const int* in_sizes, int n_in,
                              void* d_out, int out_size)
{
    const int4* x    = (const int4*)d_in[0];
    const int4* w    = (const int4*)d_in[1];
    const int*  bias = (const int*)d_in[2];
    const float* sin_ = (const float*)d_in[3];
    const float* sw_  = (const float*)d_in[4];
    const float* sout = (const float*)d_in[5];
    const float* sb_  = (const float*)d_in[6];

    const int rows = in_sizes[0] / L_SEQ;   // B*D = 8192
    qconv_silu_kernel<<<rows, TPB>>>(x, w, bias, sin_, sw_, sout, sb_,
                                     (float4*)d_out);
}

// round 8
// speedup vs baseline: 1.2686x; 1.0226x over previous
#include <cuda_runtime.h>

static constexpr int D_CH  = 4096;   // channels
static constexpr int L_SEQ = 4096;   // sequence length
static constexpr int TPB   = 256;    // 8 warps; warp owns contiguous 512-elem segment
static constexpr int V4_PER_ROW = L_SEQ / 4;  // 1024 int4 per row

// pack low bytes of 4 int32 (each in [-128,127]) into one word: b0=a,b1=b,b2=c,b3=d
__device__ __forceinline__ int pack4(int a, int b, int c, int d) {
    const unsigned lo = __byte_perm((unsigned)a, (unsigned)b, 0x0040);
    const unsigned hi = __byte_perm((unsigned)c, (unsigned)d, 0x0040);
    return (int)__byte_perm(lo, hi, 0x5410);
}

__global__ void __launch_bounds__(TPB)
qconv_silu_kernel(const int4* __restrict__ x,      // int8 promoted to int32
                  const int4* __restrict__ w,      // [D,4] int32
                  const int*  __restrict__ bias,   // [D] int32
                  const float* __restrict__ p_sin,
                  const float* __restrict__ p_sw,
                  const float* __restrict__ p_sout,
                  const float* __restrict__ p_sb,
                  float4* __restrict__ out)        // float32 out
{
    const int  row  = blockIdx.x;            // b*D + d
    const int  d    = row & (D_CH - 1);
    const int  lane = threadIdx.x & 31;
    const int  wp   = threadIdx.x >> 5;
    const long rowb = (long)row * V4_PER_ROW;
    const int  segb = 128 * wp;              // warp's first int4 within row

    // Coalesced evict-first loads: 4 lines per LDG.128
    int4 c[4];
#pragma unroll
    for (int k = 0; k < 4; ++k)
        c[k] = __ldcs(&x[rowb + segb + 32 * k + lane]);

    // Carry chunk preceding the warp segment (zeros at row start = causal pad);
    // only lane 31 (shuffle sender for lane 0) needs real data.
    int4 carry = make_int4(0, 0, 0, 0);
    if (lane == 31 && wp != 0)
        carry = __ldg(&x[rowb + segb - 1]);

    // Pack chunks and weights to bytes for dp4a
    int pk[4];
#pragma unroll
    for (int k = 0; k < 4; ++k)
        pk[k] = pack4(c[k].x, c[k].y, c[k].z, c[k].w);
    const int pc = pack4(carry.x, carry.y, carry.z, carry.w);

    const int4  wv4 = w[d];
    const int   wpk = pack4(wv4.x, wv4.y, wv4.z, wv4.w);  // b0=w0..b3=w3
    const float sxw     = __ldg(p_sin) * __ldg(p_sw);
    const float bf      = (float)bias[d] * __ldg(p_sb);
    const float inv_out = 1.0f / __ldg(p_sout);

    const int src = (lane + 31) & 31;        // rotate-up: lane 0 receives from lane 31

#pragma unroll
    for (int k = 0; k < 4; ++k) {
        // previous packed chunk: lanes 1..31 <- neighbor's pk[k]; lane 0 <- lane31's pk[k-1]/carry
        const int v  = (lane == 31) ? (k == 0 ? pc : pk[k - 1]) : pk[k];
        const int Pp = __shfl_sync(0xffffffffu, v, src);
        const int P  = pk[k];

        float4 o;
        float* op = (float*)&o;
#pragma unroll
        for (int j = 0; j < 4; ++j) {
            // window bytes (LSB..MSB) = x[l-3], x[l-2], x[l-1], x[l]
            const int win = (j == 3) ? P
                          : (int)__funnelshift_r((unsigned)Pp, (unsigned)P, 8 * (j + 1));
            // exact 4-tap cross-correlation in one dp4a (|acc| <= 65024)
            const int acc = __dp4a(win, wpk, 0);
            const float y = (float)acc * sxw + bf;
            // SiLU: y * sigmoid(y) via fast rcp; |y| <= ~7.8
            const float s = __fdividef(y, 1.0f + __expf(-y));
            // requant: half-even rounding matches jnp.round.
            // Lower clip provably never binds (silu >= -0.2785 -> r >= -5.6).
            const float r = rintf(s * inv_out);
            op[j] = fminf(r, 127.0f);
        }
        __stcs(&out[rowb + segb + 32 * k + lane], o);
    }
}

extern "C" void kernel_launch(void* const* d_in, const int* in_sizes, int n_in,
                              void* d_out, int out_size)
{
    const int4* x    = (const int4*)d_in[0];
    const int4* w    = (const int4*)d_in[1];
    const int*  bias = (const int*)d_in[2];
    const float* sin_ = (const float*)d_in[3];
    const float* sw_  = (const float*)d_in[4];
    const float* sout = (const float*)d_in[5];
    const float* sb_  = (const float*)d_in[6];

    const int rows = in_sizes[0] / L_SEQ;   // B*D = 8192
    qconv_silu_kernel<<<rows, TPB>>>(x, w, bias, sin_, sw_, sout, sb_,
                                     (float4*)d_out);
}